// round 1
// baseline (speedup 1.0000x reference)
#include <cuda_runtime.h>
#include <cuda_bf16.h>
#include <cstddef>

// Problem constants (fixed shapes per reference)
#define BB   4096      // batch
#define NN   8192      // nodes
#define DD   256       // feature dim
#define LL   3         // layers

// -------------------- device scratch (no allocations allowed) --------------------
__device__ int   g_labels_s[BB];
__device__ int   g_idx_s[BB];
__device__ float g_h0[(size_t)BB * DD];
__device__ float g_h1[(size_t)BB * DD];

// -------------------- 1) stable partition: positives first --------------------
// One block, 1024 threads, 4 elements each. Hillis-Steele inclusive scan of
// per-thread positive counts gives each thread its exclusive positive offset.
__global__ void sort_kernel(const int* __restrict__ labels,
                            const int* __restrict__ nidx,
                            float* __restrict__ out_labels /* may be null */) {
    __shared__ int sc[1024];
    int tid = threadIdx.x;
    int g0  = tid * 4;
    int lab[4], nd[4];
    int c = 0;
#pragma unroll
    for (int j = 0; j < 4; j++) {
        lab[j] = labels[g0 + j];
        nd[j]  = nidx[g0 + j];
        c += (lab[j] != 0);
    }
    sc[tid] = c;
    __syncthreads();
    for (int off = 1; off < 1024; off <<= 1) {
        int v   = sc[tid];
        int add = (tid >= off) ? sc[tid - off] : 0;
        __syncthreads();
        sc[tid] = v + add;
        __syncthreads();
    }
    int total = sc[1023];          // number of positives
    int p     = sc[tid] - c;       // exclusive positive prefix for this thread
#pragma unroll
    for (int j = 0; j < 4; j++) {
        int g = g0 + j;
        int dst;
        if (lab[j]) { dst = p; p++; }
        else        { dst = total + (g - p); }   // negatives keep original order
        g_labels_s[dst] = lab[j];
        g_idx_s[dst]    = nd[j];
        if (out_labels) out_labels[dst] = (float)lab[j];
    }
}

// -------------------- 2) gather + row-normalized A@E (fused rowsum) --------------------
// Block handles R=8 consecutive sorted rows. 256 threads:
//   tx = t & 63  -> 4 output columns (tx*4 .. tx*4+3)
//   ty = t >> 6  -> 2 rows (ty*2, ty*2+1)
// K tiled by 128 into smem As[8][128]; each warp loads (and partial-sums) one A row.
// Negative rows: direct E gather (fast path if whole block negative).
__global__ void gemm1_kernel(const float* __restrict__ A,
                             const float* __restrict__ E,
                             float* __restrict__ h0) {
    const int r0 = blockIdx.x * 8;
    const int t  = threadIdx.x;
    const int tx = t & 63;
    const int ty = t >> 6;

    __shared__ int   s_node[8];
    __shared__ int   s_lab[8];
    __shared__ float s_rsum[8];
    __shared__ float As[8][128];

    if (t < 8) {
        s_lab[t]  = g_labels_s[r0 + t];
        s_node[t] = g_idx_s[r0 + t];
    }
    __syncthreads();

    // All-negative block (labels are sorted descending): pure gather.
    if (s_lab[0] == 0) {
#pragma unroll
        for (int rr = 0; rr < 2; rr++) {
            int r = ty * 2 + rr;
            float4 v = *reinterpret_cast<const float4*>(
                E + (size_t)s_node[r] * DD + tx * 4);
            *reinterpret_cast<float4*>(h0 + (size_t)(r0 + r) * DD + tx * 4) = v;
        }
        return;
    }

    const int lrow = t >> 5;   // 0..7: which A row this warp loads
    const int lq   = t & 31;   // quad within row tile
    const float* Arow = A + (size_t)s_node[lrow] * NN;

    float4 acc0 = make_float4(0.f, 0.f, 0.f, 0.f);
    float4 acc1 = make_float4(0.f, 0.f, 0.f, 0.f);
    float  rsum_part = 0.f;
    const int ty2 = ty * 2;

    for (int k0 = 0; k0 < NN; k0 += 128) {
        float4 a4 = *reinterpret_cast<const float4*>(Arow + k0 + lq * 4);
        *reinterpret_cast<float4*>(&As[lrow][lq * 4]) = a4;
        rsum_part += a4.x + a4.y + a4.z + a4.w;
        __syncthreads();
#pragma unroll 16
        for (int kk = 0; kk < 128; kk++) {
            float4 e4 = __ldg(reinterpret_cast<const float4*>(
                E + (size_t)(k0 + kk) * DD + tx * 4));
            float a0 = As[ty2][kk];
            float a1 = As[ty2 + 1][kk];
            acc0.x = fmaf(a0, e4.x, acc0.x);
            acc0.y = fmaf(a0, e4.y, acc0.y);
            acc0.z = fmaf(a0, e4.z, acc0.z);
            acc0.w = fmaf(a0, e4.w, acc0.w);
            acc1.x = fmaf(a1, e4.x, acc1.x);
            acc1.y = fmaf(a1, e4.y, acc1.y);
            acc1.z = fmaf(a1, e4.z, acc1.z);
            acc1.w = fmaf(a1, e4.w, acc1.w);
        }
        __syncthreads();
    }

    // row sums: one warp per row, tree-reduce the per-lane partials
#pragma unroll
    for (int off = 16; off > 0; off >>= 1)
        rsum_part += __shfl_down_sync(0xffffffffu, rsum_part, off);
    if (lq == 0) s_rsum[lrow] = rsum_part;
    __syncthreads();

#pragma unroll
    for (int rr = 0; rr < 2; rr++) {
        int r  = ty2 + rr;
        int gr = r0 + r;
        float4 o;
        if (s_lab[r]) {
            float inv = 1.f / s_rsum[r];
            float4 a  = rr ? acc1 : acc0;
            o.x = a.x * inv; o.y = a.y * inv; o.z = a.z * inv; o.w = a.w * inv;
        } else {
            o = *reinterpret_cast<const float4*>(
                E + (size_t)s_node[r] * DD + tx * 4);
        }
        *reinterpret_cast<float4*>(h0 + (size_t)gr * DD + tx * 4) = o;
    }
}

// -------------------- 3) Linear + ReLU: out = relu(in @ W^T + b) --------------------
// 64x64 output tile per block, 256 threads, 4x4 micro-tile, K tiled by 16.
// Both operands staged transposed in smem so inner loop is 2x LDS.128 + 16 FFMA.
__global__ void mlp_kernel(const float* __restrict__ in,
                           const float* __restrict__ W,
                           const float* __restrict__ bias,
                           float* __restrict__ out) {
    const int i0 = blockIdx.x * 64;
    const int o0 = blockIdx.y * 64;
    const int t  = threadIdx.x;
    const int tx = t % 16;   // 4 output cols: o0 + tx*4 ..
    const int ty = t / 16;   // 4 output rows: i0 + ty*4 ..

    __shared__ float HsT[16][68];   // [kk][row], 68*4=272B rows keep 16B alignment
    __shared__ float WsT[16][68];   // [kk][ocol]

    float acc[4][4];
#pragma unroll
    for (int i = 0; i < 4; i++)
#pragma unroll
        for (int j = 0; j < 4; j++) acc[i][j] = 0.f;

    const int lrow = t >> 2;   // 0..63
    const int lseg = t & 3;    // k segment (4 floats)

    for (int k0 = 0; k0 < DD; k0 += 16) {
        float4 hv = *reinterpret_cast<const float4*>(
            in + (size_t)(i0 + lrow) * DD + k0 + lseg * 4);
        float4 wv = *reinterpret_cast<const float4*>(
            W + (size_t)(o0 + lrow) * DD + k0 + lseg * 4);
        HsT[lseg * 4 + 0][lrow] = hv.x;
        HsT[lseg * 4 + 1][lrow] = hv.y;
        HsT[lseg * 4 + 2][lrow] = hv.z;
        HsT[lseg * 4 + 3][lrow] = hv.w;
        WsT[lseg * 4 + 0][lrow] = wv.x;
        WsT[lseg * 4 + 1][lrow] = wv.y;
        WsT[lseg * 4 + 2][lrow] = wv.z;
        WsT[lseg * 4 + 3][lrow] = wv.w;
        __syncthreads();
#pragma unroll
        for (int kk = 0; kk < 16; kk++) {
            float4 a  = *reinterpret_cast<const float4*>(&HsT[kk][ty * 4]);
            float4 bv = *reinterpret_cast<const float4*>(&WsT[kk][tx * 4]);
            acc[0][0] = fmaf(a.x, bv.x, acc[0][0]);
            acc[0][1] = fmaf(a.x, bv.y, acc[0][1]);
            acc[0][2] = fmaf(a.x, bv.z, acc[0][2]);
            acc[0][3] = fmaf(a.x, bv.w, acc[0][3]);
            acc[1][0] = fmaf(a.y, bv.x, acc[1][0]);
            acc[1][1] = fmaf(a.y, bv.y, acc[1][1]);
            acc[1][2] = fmaf(a.y, bv.z, acc[1][2]);
            acc[1][3] = fmaf(a.y, bv.w, acc[1][3]);
            acc[2][0] = fmaf(a.z, bv.x, acc[2][0]);
            acc[2][1] = fmaf(a.z, bv.y, acc[2][1]);
            acc[2][2] = fmaf(a.z, bv.z, acc[2][2]);
            acc[2][3] = fmaf(a.z, bv.w, acc[2][3]);
            acc[3][0] = fmaf(a.w, bv.x, acc[3][0]);
            acc[3][1] = fmaf(a.w, bv.y, acc[3][1]);
            acc[3][2] = fmaf(a.w, bv.z, acc[3][2]);
            acc[3][3] = fmaf(a.w, bv.w, acc[3][3]);
        }
        __syncthreads();
    }

    float b0 = bias[o0 + tx * 4 + 0];
    float b1 = bias[o0 + tx * 4 + 1];
    float b2 = bias[o0 + tx * 4 + 2];
    float b3 = bias[o0 + tx * 4 + 3];
#pragma unroll
    for (int ii = 0; ii < 4; ii++) {
        int row = i0 + ty * 4 + ii;
        float4 o;
        o.x = fmaxf(acc[ii][0] + b0, 0.f);
        o.y = fmaxf(acc[ii][1] + b1, 0.f);
        o.z = fmaxf(acc[ii][2] + b2, 0.f);
        o.w = fmaxf(acc[ii][3] + b3, 0.f);
        *reinterpret_cast<float4*>(out + (size_t)row * DD + o0 + tx * 4) = o;
    }
}

// -------------------- launch --------------------
extern "C" void kernel_launch(void* const* d_in, const int* in_sizes, int n_in,
                              void* d_out, int out_size) {
    const int*   labels = (const int*)d_in[0];
    const int*   nidx   = (const int*)d_in[1];
    const float* A      = (const float*)d_in[2];
    const float* E      = (const float*)d_in[3];
    const float* W      = (const float*)d_in[4];
    const float* bias   = (const float*)d_in[5];

    float* out        = (float*)d_out;
    float* out_labels = nullptr;
    float* out_h      = out;
    if (out_size >= BB * DD + BB) {   // tuple (labels_sorted, h) concatenated
        out_labels = out;
        out_h      = out + BB;
    }

    float *h0, *h1;
    cudaGetSymbolAddress((void**)&h0, g_h0);
    cudaGetSymbolAddress((void**)&h1, g_h1);

    sort_kernel<<<1, 1024>>>(labels, nidx, out_labels);
    gemm1_kernel<<<BB / 8, 256>>>(A, E, h0);
    mlp_kernel<<<dim3(BB / 64, DD / 64), 256>>>(h0, W,               bias,           h1);
    mlp_kernel<<<dim3(BB / 64, DD / 64), 256>>>(h1, W + DD * DD,     bias + DD,      h0);
    mlp_kernel<<<dim3(BB / 64, DD / 64), 256>>>(h0, W + 2 * DD * DD, bias + 2 * DD,  out_h);
}

// round 3
// speedup vs baseline: 3.7241x; 3.7241x over previous
#include <cuda_runtime.h>
#include <cuda_bf16.h>
#include <cstdint>
#include <cstddef>

#define BB   4096
#define NN   8192
#define DD   256
#define LL   3

// GEMM1 tiling
#define MT      64
#define KSPLIT  4
#define KPER    (NN / KSPLIT)    // 2048
#define KC      32
#define NCHUNK  (KPER / KC)      // 64
#define A_F     (64 * 36)        // A stage floats (row pad 36)
#define B_F     (32 * 264)       // B stage floats (row pad 264)
#define STAGE_F (A_F + B_F)      // 10752 floats
#define GEMM_SMEM_BYTES (2 * STAGE_F * 4)   // 86016

// -------------------- device scratch --------------------
__device__ int   g_labels_s[BB];
__device__ int   g_idx_s[BB];
__device__ int   g_total;
__device__ float g_h0[(size_t)BB * DD];
__device__ float g_h1[(size_t)BB * DD];
__device__ float g_part[(size_t)KSPLIT * BB * DD];   // K-split partial products
__device__ float g_rsumP[KSPLIT * BB];               // K-split partial row sums

// -------------------- helpers --------------------
__device__ __forceinline__ uint32_t smem_u32(const void* p) {
    uint32_t a;
    asm("{ .reg .u64 t; cvta.to.shared.u64 t, %1; cvt.u32.u64 %0, t; }" : "=r"(a) : "l"(p));
    return a;
}
#define CP16(dst, src) \
    asm volatile("cp.async.cg.shared.global [%0], [%1], 16;" \
        :: "r"(dst), "l"(__cvta_generic_to_global(src)) : "memory")
#define CP_COMMIT() asm volatile("cp.async.commit_group;" ::: "memory")
#define CP_WAIT1()  asm volatile("cp.async.wait_group 1;" ::: "memory")

__device__ __forceinline__ float trunc_tf32(float x) {
    return __uint_as_float(__float_as_uint(x) & 0xffffe000u);
}

// ==================== 1) stable partition ====================
__global__ void sort_kernel(const int* __restrict__ labels,
                            const int* __restrict__ nidx,
                            float* __restrict__ out_labels) {
    __shared__ int sc[1024];
    int tid = threadIdx.x;
    int g0  = tid * 4;
    int lab[4], nd[4];
    int c = 0;
#pragma unroll
    for (int j = 0; j < 4; j++) {
        lab[j] = labels[g0 + j];
        nd[j]  = nidx[g0 + j];
        c += (lab[j] != 0);
    }
    sc[tid] = c;
    __syncthreads();
    for (int off = 1; off < 1024; off <<= 1) {
        int v = sc[tid];
        int add = (tid >= off) ? sc[tid - off] : 0;
        __syncthreads();
        sc[tid] = v + add;
        __syncthreads();
    }
    int total = sc[1023];
    int p     = sc[tid] - c;
    if (tid == 0) g_total = total;
#pragma unroll
    for (int j = 0; j < 4; j++) {
        int g = g0 + j;
        int dst;
        if (lab[j]) { dst = p; p++; }
        else        { dst = total + (g - p); }
        g_labels_s[dst] = lab[j];
        g_idx_s[dst]    = nd[j];
        if (out_labels) out_labels[dst] = (float)lab[j];
    }
}

// ==================== 2) gathered tf32 GEMM with K-split ====================
// CTA (mt, kb): rows m0..m0+63 (sorted positions), K slice [kb*2048, +2048).
// Computes g_part[kb][m][0:256] and g_rsumP[kb][m] (truncated-A row sums).
// 8 warps: wm = wid&3 (16-row band), wn = wid>>2 (128-col band).
__global__ void __launch_bounds__(256) gemm1_kernel(const float* __restrict__ A,
                                                    const float* __restrict__ E) {
    const int m0 = blockIdx.x * MT;
    if (m0 >= g_total) return;          // fully-negative tile: nothing to do
    const int kb = blockIdx.y;

    extern __shared__ float smem[];
    const int t    = threadIdx.x;
    const int lane = t & 31;
    const int wid  = t >> 5;
    const int wm   = wid & 3;
    const int wn   = wid >> 2;

    // ---- producer addressing ----
    const int r0  = t >> 3;             // 0..31 (also handles r0+32)
    const int seg = t & 7;              // 16B segment within 32-float row chunk
    const int node0 = g_idx_s[m0 + r0];
    const int node1 = g_idx_s[m0 + r0 + 32];
    const float* srcA0 = A + (size_t)node0 * NN + (size_t)kb * KPER + seg * 4;
    const float* srcA1 = A + (size_t)node1 * NN + (size_t)kb * KPER + seg * 4;
    const int bk0 = t >> 6;             // 0..3 (B k-row, +4j)
    const int bn4 = (t & 63) * 4;       // B n offset in floats
    const float* srcB = E + (size_t)((size_t)kb * KPER + bk0) * DD + bn4;

    const uint32_t sb  = smem_u32(smem);
    const uint32_t dA0 = (uint32_t)((r0 * 36 + seg * 4) * 4);
    const uint32_t dA1 = (uint32_t)(((r0 + 32) * 36 + seg * 4) * 4);
    const uint32_t dB0 = (uint32_t)((bk0 * 264 + (t & 63) * 4) * 4);

    float acc[16][4];
#pragma unroll
    for (int j = 0; j < 16; j++)
#pragma unroll
        for (int q = 0; q < 4; q++) acc[j][q] = 0.f;
    float rsum = 0.f;

    // ---- pipelined main loop ----
    auto load_stage = [&](int c, int s) {
        const uint32_t base = sb + (uint32_t)(s * STAGE_F * 4);
        const size_t ko = (size_t)c * KC;                 // K offset (floats)
        CP16(base + dA0, srcA0 + ko);
        CP16(base + dA1, srcA1 + ko);
        const uint32_t bbase = base + A_F * 4;
        const float* sB = srcB + ko * DD;                 // advance c*32 B rows
#pragma unroll
        for (int j = 0; j < 8; j++)
            CP16(bbase + dB0 + (uint32_t)(j * 4 * 264 * 4), sB + (size_t)j * 4 * DD);
    };

    auto compute_stage = [&](int s) {
        const float*    As  = smem + s * STAGE_F;
        const uint32_t* Asu = (const uint32_t*)As;
        const uint32_t* Bsu = (const uint32_t*)(As + A_F);
        // fused row-sum of (tf32-truncated) A tile: threads 0..63, row = t
        if (t < 64) {
            const float* rp = As + t * 36;
            float ss = 0.f;
#pragma unroll
            for (int jj = 0; jj < 32; jj++)
                ss += trunc_tf32(rp[(lane + jj) & 31]);   // staggered: conflict-free
            rsum += ss;
        }
        const int arb = wm * 16 + (lane >> 2);
        const int bnx = wn * 128 + (lane >> 2);
#pragma unroll
        for (int ks = 0; ks < 4; ks++) {
            const int ac = ks * 8 + (lane & 3);
            uint32_t a0 = Asu[arb * 36 + ac];
            uint32_t a1 = Asu[(arb + 8) * 36 + ac];
            uint32_t a2 = Asu[arb * 36 + ac + 4];
            uint32_t a3 = Asu[(arb + 8) * 36 + ac + 4];
            const int bkx = ks * 8 + (lane & 3);
#pragma unroll
            for (int j = 0; j < 16; j++) {
                uint32_t b0 = Bsu[bkx * 264 + bnx + j * 8];
                uint32_t b1 = Bsu[(bkx + 4) * 264 + bnx + j * 8];
                asm volatile(
                    "mma.sync.aligned.m16n8k8.row.col.f32.tf32.tf32.f32 "
                    "{%0,%1,%2,%3}, {%4,%5,%6,%7}, {%8,%9}, {%0,%1,%2,%3};"
                    : "+f"(acc[j][0]), "+f"(acc[j][1]), "+f"(acc[j][2]), "+f"(acc[j][3])
                    : "r"(a0), "r"(a1), "r"(a2), "r"(a3), "r"(b0), "r"(b1));
            }
        }
    };

    load_stage(0, 0);
    CP_COMMIT();
    for (int c = 0; c < NCHUNK; c++) {
        if (c + 1 < NCHUNK) load_stage(c + 1, (c + 1) & 1);
        CP_COMMIT();
        CP_WAIT1();
        __syncthreads();
        compute_stage(c & 1);
        __syncthreads();
    }

    // ---- epilogue: store partials ----
    float* pbase = g_part + ((size_t)kb * BB + m0) * DD;
    const int rr = wm * 16 + (lane >> 2);
    const int c0 = wn * 128 + (lane & 3) * 2;
#pragma unroll
    for (int j = 0; j < 16; j++) {
        float2 v0 = make_float2(acc[j][0], acc[j][1]);
        float2 v1 = make_float2(acc[j][2], acc[j][3]);
        *reinterpret_cast<float2*>(pbase + (size_t)rr * DD + c0 + j * 8)       = v0;
        *reinterpret_cast<float2*>(pbase + (size_t)(rr + 8) * DD + c0 + j * 8) = v1;
    }
    if (t < 64) g_rsumP[kb * BB + m0 + t] = rsum;
}

// ==================== 3) finalize: reduce K-splits, normalize, gather ====================
__global__ void finalize_kernel(const float* __restrict__ E, float* __restrict__ h0) {
    const int b = blockIdx.x;
    const int t = threadIdx.x;          // 64 threads x float4
    const int lab  = g_labels_s[b];
    const int node = g_idx_s[b];
    float4 o;
    if (lab) {
        float rs = g_rsumP[b] + g_rsumP[BB + b] + g_rsumP[2 * BB + b] + g_rsumP[3 * BB + b];
        float inv = 1.0f / rs;
        float4 v = make_float4(0.f, 0.f, 0.f, 0.f);
#pragma unroll
        for (int kb = 0; kb < KSPLIT; kb++) {
            float4 p = *reinterpret_cast<const float4*>(
                g_part + ((size_t)kb * BB + b) * DD + t * 4);
            v.x += p.x; v.y += p.y; v.z += p.z; v.w += p.w;
        }
        o.x = v.x * inv; o.y = v.y * inv; o.z = v.z * inv; o.w = v.w * inv;
    } else {
        o = *reinterpret_cast<const float4*>(E + (size_t)node * DD + t * 4);
    }
    *reinterpret_cast<float4*>(h0 + (size_t)b * DD + t * 4) = o;
}

// ==================== 4) Linear + ReLU (fp32 SIMT) ====================
__global__ void mlp_kernel(const float* __restrict__ in,
                           const float* __restrict__ W,
                           const float* __restrict__ bias,
                           float* __restrict__ out) {
    const int i0 = blockIdx.x * 64;
    const int o0 = blockIdx.y * 64;
    const int t  = threadIdx.x;
    const int tx = t % 16;
    const int ty = t / 16;

    __shared__ float HsT[16][68];
    __shared__ float WsT[16][68];

    float acc[4][4];
#pragma unroll
    for (int i = 0; i < 4; i++)
#pragma unroll
        for (int j = 0; j < 4; j++) acc[i][j] = 0.f;

    const int lrow = t >> 2;
    const int lseg = t & 3;

    for (int k0 = 0; k0 < DD; k0 += 16) {
        float4 hv = *reinterpret_cast<const float4*>(in + (size_t)(i0 + lrow) * DD + k0 + lseg * 4);
        float4 wv = *reinterpret_cast<const float4*>(W + (size_t)(o0 + lrow) * DD + k0 + lseg * 4);
        HsT[lseg * 4 + 0][lrow] = hv.x;
        HsT[lseg * 4 + 1][lrow] = hv.y;
        HsT[lseg * 4 + 2][lrow] = hv.z;
        HsT[lseg * 4 + 3][lrow] = hv.w;
        WsT[lseg * 4 + 0][lrow] = wv.x;
        WsT[lseg * 4 + 1][lrow] = wv.y;
        WsT[lseg * 4 + 2][lrow] = wv.z;
        WsT[lseg * 4 + 3][lrow] = wv.w;
        __syncthreads();
#pragma unroll
        for (int kk = 0; kk < 16; kk++) {
            float4 a  = *reinterpret_cast<const float4*>(&HsT[kk][ty * 4]);
            float4 bv = *reinterpret_cast<const float4*>(&WsT[kk][tx * 4]);
            acc[0][0] = fmaf(a.x, bv.x, acc[0][0]);
            acc[0][1] = fmaf(a.x, bv.y, acc[0][1]);
            acc[0][2] = fmaf(a.x, bv.z, acc[0][2]);
            acc[0][3] = fmaf(a.x, bv.w, acc[0][3]);
            acc[1][0] = fmaf(a.y, bv.x, acc[1][0]);
            acc[1][1] = fmaf(a.y, bv.y, acc[1][1]);
            acc[1][2] = fmaf(a.y, bv.z, acc[1][2]);
            acc[1][3] = fmaf(a.y, bv.w, acc[1][3]);
            acc[2][0] = fmaf(a.z, bv.x, acc[2][0]);
            acc[2][1] = fmaf(a.z, bv.y, acc[2][1]);
            acc[2][2] = fmaf(a.z, bv.z, acc[2][2]);
            acc[2][3] = fmaf(a.z, bv.w, acc[2][3]);
            acc[3][0] = fmaf(a.w, bv.x, acc[3][0]);
            acc[3][1] = fmaf(a.w, bv.y, acc[3][1]);
            acc[3][2] = fmaf(a.w, bv.z, acc[3][2]);
            acc[3][3] = fmaf(a.w, bv.w, acc[3][3]);
        }
        __syncthreads();
    }

    float b0 = bias[o0 + tx * 4 + 0];
    float b1 = bias[o0 + tx * 4 + 1];
    float b2 = bias[o0 + tx * 4 + 2];
    float b3 = bias[o0 + tx * 4 + 3];
#pragma unroll
    for (int ii = 0; ii < 4; ii++) {
        int row = i0 + ty * 4 + ii;
        float4 o;
        o.x = fmaxf(acc[ii][0] + b0, 0.f);
        o.y = fmaxf(acc[ii][1] + b1, 0.f);
        o.z = fmaxf(acc[ii][2] + b2, 0.f);
        o.w = fmaxf(acc[ii][3] + b3, 0.f);
        *reinterpret_cast<float4*>(out + (size_t)row * DD + o0 + tx * 4) = o;
    }
}

// ==================== launch ====================
extern "C" void kernel_launch(void* const* d_in, const int* in_sizes, int n_in,
                              void* d_out, int out_size) {
    const int*   labels = (const int*)d_in[0];
    const int*   nidx   = (const int*)d_in[1];
    const float* A      = (const float*)d_in[2];
    const float* E      = (const float*)d_in[3];
    const float* W      = (const float*)d_in[4];
    const float* bias   = (const float*)d_in[5];

    float* out        = (float*)d_out;
    float* out_labels = nullptr;
    float* out_h      = out;
    if (out_size >= BB * DD + BB) {
        out_labels = out;
        out_h      = out + BB;
    }

    float *h0, *h1;
    cudaGetSymbolAddress((void**)&h0, g_h0);
    cudaGetSymbolAddress((void**)&h1, g_h1);

    cudaFuncSetAttribute(gemm1_kernel,
                         cudaFuncAttributeMaxDynamicSharedMemorySize, GEMM_SMEM_BYTES);

    sort_kernel<<<1, 1024>>>(labels, nidx, out_labels);
    gemm1_kernel<<<dim3(BB / MT, KSPLIT), 256, GEMM_SMEM_BYTES>>>(A, E);
    finalize_kernel<<<BB, 64>>>(E, h0);
    mlp_kernel<<<dim3(BB / 64, DD / 64), 256>>>(h0, W,               bias,          h1);
    mlp_kernel<<<dim3(BB / 64, DD / 64), 256>>>(h1, W + DD * DD,     bias + DD,     h0);
    mlp_kernel<<<dim3(BB / 64, DD / 64), 256>>>(h0, W + 2 * DD * DD, bias + 2 * DD, out_h);
}